// round 5
// baseline (speedup 1.0000x reference)
#include <cuda_runtime.h>

// ---------------------------------------------------------------------------
// SSIM fusion loss: 1 - (SSIM(f,s1)+SSIM(f,s2))/2, single fused kernel.
// Separable 11-tap Gaussian blur; FFMA-imm weights (compile-time literals);
// smem aliasing (hintB over consumed raw rows) -> 56.2KB -> 4 CTAs/SM.
// Deterministic Q32 fixed-point reduction + last-block finalize.
// ---------------------------------------------------------------------------

#define IMH 512
#define IMW 512
#define TW 32
#define TH 32
#define EXT 42
#define PSTR 43                  // cols per plane row (42 data + 1 pad)
#define RS3 129                  // raw row stride = 3*PSTR (interleaved planes)
#define HSTR 36
#define R1 30                    // hintA rows (0..29)
#define HA_BASE 5420             // floats; 16B aligned (5420*4 % 16 == 0)
#define HA_FSTR (R1*HSTR)        // 1080 floats per field (hintA)
#define HB_FSTR (12*HSTR)        // 432 floats per field (hintB, aliased at smem[0])
#define NTHREADS 256
#define GX 16
#define GY 16
#define NPLANES 48
#define NBLOCKS (GX*GY*NPLANES)
#define NTOT 12582912.0
#define FPSCALE 4294967296.0
#define SMEM_FLOATS (HA_BASE + 8*HA_FSTR)   // 5420 + 8640 = 14060
#define SMEM_BYTES  (SMEM_FLOATS*4)         // 56240 B -> 4 CTAs/SM

typedef unsigned long long u64;

__device__ u64      g_acc   = 0ULL;
__device__ unsigned g_count = 0u;

// Gaussian weights (sigma=1.5, 11 taps, normalized) as compile-time constants
// -> ptxas emits FFMA with immediate multiplier (rt_SMSP = 1).
__device__ constexpr float WT[6] = {
    0.00102838f, 0.00759876f, 0.03600077f,
    0.10936069f, 0.21300554f, 0.26601173f
};
#define WTAP(j) WT[((j) < 6) ? (j) : (10 - (j))]

#define HPASS_BODY(RAWROW, STOREBASE, FSTRIDE)                                \
{                                                                             \
    float acc[8][4];                                                          \
    _Pragma("unroll")                                                         \
    for (int k = 0; k < 8; ++k)                                               \
        _Pragma("unroll")                                                     \
        for (int o = 0; o < 4; ++o) acc[k][o] = 0.f;                          \
    _Pragma("unroll")                                                         \
    for (int cc = 0; cc < 14; ++cc) {                                         \
        float f = (RAWROW)[0*PSTR + c0 + cc];                                 \
        float a = (RAWROW)[1*PSTR + c0 + cc];                                 \
        float b = (RAWROW)[2*PSTR + c0 + cc];                                 \
        float v3 = f*f, v4 = a*a, v5 = b*b, v6 = f*a, v7 = f*b;               \
        _Pragma("unroll")                                                     \
        for (int o = 0; o < 4; ++o) {                                         \
            const int j = cc - o;                                             \
            if (j >= 0 && j < 11) {                                           \
                const float w = WTAP(j);                                      \
                acc[0][o] += w * f;   acc[1][o] += w * a;                     \
                acc[2][o] += w * b;   acc[3][o] += w * v3;                    \
                acc[4][o] += w * v4;  acc[5][o] += w * v5;                    \
                acc[6][o] += w * v6;  acc[7][o] += w * v7;                    \
            }                                                                 \
        }                                                                     \
    }                                                                         \
    _Pragma("unroll")                                                         \
    for (int k = 0; k < 8; ++k) {                                             \
        float4 st = make_float4(acc[k][0], acc[k][1], acc[k][2], acc[k][3]);  \
        *reinterpret_cast<float4*>((STOREBASE) + k*(FSTRIDE)) = st;           \
    }                                                                         \
}

__global__ __launch_bounds__(NTHREADS, 4)
void ssim_fused_kernel(const float* __restrict__ F,
                       const float* __restrict__ S1,
                       const float* __restrict__ S2,
                       float* __restrict__ out)
{
    extern __shared__ float smem[];
    // layout: [0 .. 5418) raw[42][3][43]  (rows 0..29 later aliased by hintB)
    //         [HA_BASE ..) hintA[8][30][36]
    //         hintB[8][12][36] at smem[0] (over consumed raw rows 0..29)

    const int tid  = threadIdx.x;
    const int wid  = tid >> 5;
    const int lane = tid & 31;

    const int bx = blockIdx.x, by = blockIdx.y, bz = blockIdx.z;
    const int plane = bz * (IMH * IMW);
    const int x0 = bx * TW - 5;
    const int y0 = by * TH - 5;

    // ---- Load 42x42x3 halo tile (warp per row, interleaved layout) --------
    const float* srcs[3] = {F, S1, S2};
    for (int r = wid; r < EXT; r += 8) {
        const int gy = y0 + r;
        const bool rowok = (gy >= 0) && (gy < IMH);
        const int rowoff = plane + gy * IMW + x0;
        float* dst = smem + r * RS3;
        #pragma unroll
        for (int p = 0; p < 3; ++p) {
            const float* s = srcs[p];
            {   // cols 0..31
                int c = lane;
                int gx = x0 + c;
                bool ok = rowok && (gx >= 0) && (gx < IMW);
                dst[p*PSTR + c] = ok ? __ldg(s + rowoff + c) : 0.f;
            }
            if (lane < EXT - 32) {  // cols 32..41
                int c = lane + 32;
                int gx = x0 + c;
                bool ok = rowok && (gx >= 0) && (gx < IMW);
                dst[p*PSTR + c] = ok ? __ldg(s + rowoff + c) : 0.f;
            }
        }
    }
    __syncthreads();

    // ---- Horizontal pass, chunk A: hint rows 0..29 -> hintA ---------------
    if (tid < R1 * 8) {
        const int r  = tid >> 3;
        const int c0 = (tid & 7) * 4;
        const float* rawrow = smem + r * RS3;
        float* sb = smem + HA_BASE + r * HSTR + c0;
        HPASS_BODY(rawrow, sb, HA_FSTR)
    }
    __syncthreads();

    // ---- Horizontal pass, chunk B: hint rows 30..41 -> hintB (alias raw 0..29)
    if (tid < 12 * 8) {
        const int rr = tid >> 3;            // 0..11 -> row 30+rr
        const int c0 = (tid & 7) * 4;
        const float* rawrow = smem + (R1 + rr) * RS3;
        float* sb = smem + rr * HSTR + c0;  // hintB base = smem[0]
        HPASS_BODY(rawrow, sb, HB_FSTR)
    }
    __syncthreads();

    // ---- Vertical pass + SSIM: thread = 1 col x 4 output rows -------------
    const int col = lane;
    const int r0v = wid * 4;

    float acc[8][4];
    #pragma unroll
    for (int k = 0; k < 8; ++k)
        #pragma unroll
        for (int o = 0; o < 4; ++o) acc[k][o] = 0.f;

    #pragma unroll
    for (int jj = 0; jj < 14; ++jj) {
        const int row = r0v + jj;
        const bool inA = (row < R1);
        const int ra = HA_BASE + row * HSTR + col;
        const int rb = (row - R1) * HSTR + col;
        #pragma unroll
        for (int k = 0; k < 8; ++k) {
            float v = smem[inA ? (ra + k*HA_FSTR) : (rb + k*HB_FSTR)];
            #pragma unroll
            for (int o = 0; o < 4; ++o) {
                const int j = jj - o;
                if (j >= 0 && j < 11)
                    acc[k][o] += WTAP(j) * v;
            }
        }
    }

    const float C1 = 1e-4f;
    const float C2 = 9e-4f;
    float lsum = 0.f;
    #pragma unroll
    for (int o = 0; o < 4; ++o) {
        float muF = acc[0][o], mu1 = acc[1][o], mu2 = acc[2][o];
        float eFF = acc[3][o], e11 = acc[4][o], e22 = acc[5][o];
        float eF1 = acc[6][o], eF2 = acc[7][o];

        float mFF = muF*muF, m11 = mu1*mu1, m22 = mu2*mu2;
        float pF1 = muF*mu1, pF2 = muF*mu2;

        float sF  = eFF - mFF;
        float s11 = e11 - m11;
        float s22 = e22 - m22;
        float c1v = eF1 - pF1;
        float c2v = eF2 - pF2;

        float num1 = (2.f*pF1 + C1) * (2.f*c1v + C2);
        float den1 = (mFF + m11 + C1) * (sF + s11 + C2);
        float num2 = (2.f*pF2 + C1) * (2.f*c2v + C2);
        float den2 = (mFF + m22 + C1) * (sF + s22 + C2);

        lsum += __fdividef(num1*den2 + num2*den1, den1*den2);
    }

    // ---- Reduction: warp shuffle -> block -> global Q32 atomic ------------
    #pragma unroll
    for (int off = 16; off > 0; off >>= 1)
        lsum += __shfl_xor_sync(0xffffffffu, lsum, off);

    __shared__ float warpsum[8];
    if (lane == 0) warpsum[wid] = lsum;
    __syncthreads();
    if (tid == 0) {
        double s = 0.0;
        #pragma unroll
        for (int i = 0; i < 8; ++i) s += (double)warpsum[i];
        long long q = __double2ll_rn(s * FPSCALE);
        atomicAdd(&g_acc, (u64)q);
        __threadfence();
        unsigned ticket = atomicInc(&g_count, NBLOCKS - 1);
        if (ticket == NBLOCKS - 1) {
            u64 v = atomicExch(&g_acc, 0ULL);   // read + reset for next replay
            out[0] = (float)(1.0 - ((double)(long long)v * (1.0/FPSCALE))
                                   / (2.0 * NTOT));
        }
    }
}

extern "C" void kernel_launch(void* const* d_in, const int* in_sizes, int n_in,
                              void* d_out, int out_size)
{
    const float* F  = (const float*)d_in[0];
    const float* S1 = (const float*)d_in[1];
    const float* S2 = (const float*)d_in[2];

    static bool attr_set = false;
    if (!attr_set) {
        cudaFuncSetAttribute(ssim_fused_kernel,
                             cudaFuncAttributeMaxDynamicSharedMemorySize,
                             SMEM_BYTES);
        attr_set = true;
    }

    dim3 grid(GX, GY, NPLANES);
    ssim_fused_kernel<<<grid, NTHREADS, SMEM_BYTES>>>(F, S1, S2, (float*)d_out);
}

// round 6
// speedup vs baseline: 1.3250x; 1.3250x over previous
#include <cuda_runtime.h>

// ---------------------------------------------------------------------------
// SSIM fusion loss: 1 - (SSIM(f,s1)+SSIM(f,s2))/2, single fused kernel.
// R2-proven layout (3 CTAs/SM, no reg cap) + FFMA-imm literal weights +
// deterministic Q32 fixed-point reduction with last-block finalize.
// ---------------------------------------------------------------------------

#define IMH 512
#define IMW 512
#define TW 32
#define TH 32
#define EXT 42
#define RSTR 43                  // raw plane row stride (odd -> conflict free)
#define HSTR 36                  // hint plane row stride (16B-aligned cols)
#define HBASE 5420               // hint base (floats); 16B aligned, > 3*EXT*RSTR=5418
#define NTHREADS 256
#define GX 16
#define GY 16
#define NPLANES 48
#define NBLOCKS (GX*GY*NPLANES)
#define NTOT 12582912.0
#define FPSCALE 4294967296.0
#define SMEM_FLOATS (HBASE + 8*EXT*HSTR)    // 5420 + 12096 = 17516
#define SMEM_BYTES  (SMEM_FLOATS*4)         // 70064 B -> 3 CTAs/SM

typedef unsigned long long u64;

__device__ u64      g_acc   = 0ULL;
__device__ unsigned g_count = 0u;

// Gaussian weights (sigma=1.5, 11 taps, normalized), symmetric: w[j]=w[10-j].
// Compile-time literals -> ptxas emits FFMA with immediate multiplier (rt=1).
#define W0 0.00102838f
#define W1 0.00759876f
#define W2 0.03600077f
#define W3 0.10936069f
#define W4 0.21300554f
#define W5 0.26601173f
__device__ constexpr float WT[11] = { W0,W1,W2,W3,W4,W5,W4,W3,W2,W1,W0 };

__global__ __launch_bounds__(NTHREADS)
void ssim_fused_kernel(const float* __restrict__ F,
                       const float* __restrict__ S1,
                       const float* __restrict__ S2,
                       float* __restrict__ out)
{
    extern __shared__ float smem[];
    float* raw  = smem;              // [3][EXT*RSTR]
    float* hint = smem + HBASE;      // [8][EXT*HSTR]

    const int tid  = threadIdx.x;
    const int wid  = tid >> 5;
    const int lane = tid & 31;

    const int bx = blockIdx.x, by = blockIdx.y, bz = blockIdx.z;
    const int plane = bz * (IMH * IMW);
    const int x0 = bx * TW - 5;
    const int y0 = by * TH - 5;

    // ---- Load 42x42 halo tile of f, s1, s2 (warp per row) -----------------
    for (int r = wid; r < EXT; r += 8) {
        const int gy = y0 + r;
        const bool rowok = (gy >= 0) && (gy < IMH);
        const int rowoff = plane + gy * IMW;
        #pragma unroll
        for (int half = 0; half < 2; ++half) {
            int c = lane + half * 32;
            if (c < EXT) {
                int gx = x0 + c;
                bool ok = rowok && (gx >= 0) && (gx < IMW);
                int off = rowoff + gx;
                raw[0*EXT*RSTR + r*RSTR + c] = ok ? __ldg(F  + off) : 0.f;
                raw[1*EXT*RSTR + r*RSTR + c] = ok ? __ldg(S1 + off) : 0.f;
                raw[2*EXT*RSTR + r*RSTR + c] = ok ? __ldg(S2 + off) : 0.f;
            }
        }
    }
    __syncthreads();

    // ---- Horizontal pass: 336 tasks (42 rows x 8 groups of 4 cols) --------
    for (int task = tid; task < EXT * 8; task += NTHREADS) {
        const int r  = task >> 3;
        const int c0 = (task & 7) * 4;

        float acc[8][4];
        #pragma unroll
        for (int k = 0; k < 8; ++k)
            #pragma unroll
            for (int o = 0; o < 4; ++o) acc[k][o] = 0.f;

        const float* r0p = &raw[0*EXT*RSTR + r*RSTR + c0];
        const float* r1p = &raw[1*EXT*RSTR + r*RSTR + c0];
        const float* r2p = &raw[2*EXT*RSTR + r*RSTR + c0];

        #pragma unroll
        for (int cc = 0; cc < 14; ++cc) {
            float f = r0p[cc], a = r1p[cc], b = r2p[cc];
            float v3 = f*f, v4 = a*a, v5 = b*b, v6 = f*a, v7 = f*b;
            #pragma unroll
            for (int o = 0; o < 4; ++o) {
                const int j = cc - o;
                if (j >= 0 && j < 11) {
                    const float w = WT[j];
                    acc[0][o] += w * f;   acc[1][o] += w * a;
                    acc[2][o] += w * b;   acc[3][o] += w * v3;
                    acc[4][o] += w * v4;  acc[5][o] += w * v5;
                    acc[6][o] += w * v6;  acc[7][o] += w * v7;
                }
            }
        }
        #pragma unroll
        for (int k = 0; k < 8; ++k) {
            float4 st = make_float4(acc[k][0], acc[k][1], acc[k][2], acc[k][3]);
            *reinterpret_cast<float4*>(&hint[k*EXT*HSTR + r*HSTR + c0]) = st;
        }
    }
    __syncthreads();

    // ---- Vertical pass + SSIM: thread = 1 column x 4 output rows ----------
    const int col = lane;
    const int r0v = wid * 4;

    float acc[8][4];
    #pragma unroll
    for (int k = 0; k < 8; ++k)
        #pragma unroll
        for (int o = 0; o < 4; ++o) acc[k][o] = 0.f;

    #pragma unroll
    for (int jj = 0; jj < 14; ++jj) {
        float v[8];
        #pragma unroll
        for (int k = 0; k < 8; ++k)
            v[k] = hint[k*EXT*HSTR + (r0v + jj)*HSTR + col];
        #pragma unroll
        for (int o = 0; o < 4; ++o) {
            const int j = jj - o;
            if (j >= 0 && j < 11) {
                const float w = WT[j];
                #pragma unroll
                for (int k = 0; k < 8; ++k) acc[k][o] += w * v[k];
            }
        }
    }

    const float C1 = 1e-4f;
    const float C2 = 9e-4f;
    float lsum = 0.f;
    #pragma unroll
    for (int o = 0; o < 4; ++o) {
        float muF = acc[0][o], mu1 = acc[1][o], mu2 = acc[2][o];
        float eFF = acc[3][o], e11 = acc[4][o], e22 = acc[5][o];
        float eF1 = acc[6][o], eF2 = acc[7][o];

        float mFF = muF*muF, m11 = mu1*mu1, m22 = mu2*mu2;
        float pF1 = muF*mu1, pF2 = muF*mu2;

        float sF  = eFF - mFF;
        float s11 = e11 - m11;
        float s22 = e22 - m22;
        float c1v = eF1 - pF1;
        float c2v = eF2 - pF2;

        float num1 = (2.f*pF1 + C1) * (2.f*c1v + C2);
        float den1 = (mFF + m11 + C1) * (sF + s11 + C2);
        float num2 = (2.f*pF2 + C1) * (2.f*c2v + C2);
        float den2 = (mFF + m22 + C1) * (sF + s22 + C2);

        lsum += __fdividef(num1*den2 + num2*den1, den1*den2);
    }

    // ---- Reduction: warp shuffle -> block -> global Q32 atomic ------------
    #pragma unroll
    for (int off = 16; off > 0; off >>= 1)
        lsum += __shfl_xor_sync(0xffffffffu, lsum, off);

    __shared__ float warpsum[8];
    if (lane == 0) warpsum[wid] = lsum;
    __syncthreads();
    if (tid == 0) {
        double s = 0.0;
        #pragma unroll
        for (int i = 0; i < 8; ++i) s += (double)warpsum[i];
        long long q = __double2ll_rn(s * FPSCALE);
        atomicAdd(&g_acc, (u64)q);
        __threadfence();
        unsigned ticket = atomicInc(&g_count, NBLOCKS - 1);
        if (ticket == NBLOCKS - 1) {
            u64 v = atomicExch(&g_acc, 0ULL);   // read + reset for next replay
            out[0] = (float)(1.0 - ((double)(long long)v * (1.0/FPSCALE))
                                   / (2.0 * NTOT));
        }
    }
}

extern "C" void kernel_launch(void* const* d_in, const int* in_sizes, int n_in,
                              void* d_out, int out_size)
{
    const float* F  = (const float*)d_in[0];
    const float* S1 = (const float*)d_in[1];
    const float* S2 = (const float*)d_in[2];

    static bool attr_set = false;
    if (!attr_set) {
        cudaFuncSetAttribute(ssim_fused_kernel,
                             cudaFuncAttributeMaxDynamicSharedMemorySize,
                             SMEM_BYTES);
        attr_set = true;
    }

    dim3 grid(GX, GY, NPLANES);
    ssim_fused_kernel<<<grid, NTHREADS, SMEM_BYTES>>>(F, S1, S2, (float*)d_out);
}

// round 7
// speedup vs baseline: 1.4018x; 1.0580x over previous
#include <cuda_runtime.h>

// ---------------------------------------------------------------------------
// SSIM fusion loss: 1 - (SSIM(f,s1)+SSIM(f,s2))/2, single fused kernel.
// R2-proven smem layout (3 CTAs/SM), vectorized LDG.128 halo load,
// guaranteed-immediate Gaussian weights, deterministic Q32 reduction
// across 48 slots with parallel last-block finalize.
// ---------------------------------------------------------------------------

#define IMH 512
#define IMW 512
#define TW 32
#define TH 32
#define EXT 42
#define RSTR 43                  // raw plane row stride (odd -> conflict free)
#define HSTR 36                  // hint plane row stride (16B-aligned cols)
#define HBASE 5420               // hint base (floats); 16B aligned, > 3*EXT*RSTR
#define NTHREADS 256
#define GX 16
#define GY 16
#define NPLANES 48
#define NBLOCKS (GX*GY*NPLANES)
#define NTOT 12582912.0
#define FPSCALE 4294967296.0
#define SMEM_FLOATS (HBASE + 8*EXT*HSTR)    // 17516
#define SMEM_BYTES  (SMEM_FLOATS*4)         // 70064 B -> 3 CTAs/SM

typedef unsigned long long u64;

__device__ u64      g_accs[NPLANES];        // zero-initialized
__device__ unsigned g_count = 0u;

// Gaussian weights (sigma=1.5, 11 taps, normalized). Pure literal macro:
// after full unroll, WW(j) is a float literal -> FFMA with immediate (rt=1).
#define W0f 0.00102838f
#define W1f 0.00759876f
#define W2f 0.03600077f
#define W3f 0.10936069f
#define W4f 0.21300554f
#define W5f 0.26601173f
#define WW(j) ( (j)==5 ? W5f : ((j)==4||(j)==6) ? W4f : ((j)==3||(j)==7) ? W3f \
              : ((j)==2||(j)==8) ? W2f : ((j)==1||(j)==9) ? W1f : W0f )

__global__ __launch_bounds__(NTHREADS)
void ssim_fused_kernel(const float* __restrict__ F,
                       const float* __restrict__ S1,
                       const float* __restrict__ S2,
                       float* __restrict__ out)
{
    extern __shared__ float smem[];
    float* raw  = smem;              // [3][EXT*RSTR]
    float* hint = smem + HBASE;      // [8][EXT*HSTR]

    const int tid  = threadIdx.x;
    const int wid  = tid >> 5;
    const int lane = tid & 31;

    const int bx = blockIdx.x, by = blockIdx.y, bz = blockIdx.z;
    const int plane = bz * (IMH * IMW);
    const int x0 = bx * TW - 5;
    const int y0 = by * TH - 5;

    // ---- Vectorized halo load: 42 rows x 3 planes x 12 float4 chunks ------
    // Loads are 16B-aligned; IMW%4==0 so each float4 is fully in- or out-of-
    // range (never partial). Scatter to raw cols with per-component masks.
    for (int i = tid; i < EXT * 3 * 12; i += NTHREADS) {
        const int q  = i % 12;             // chunk within row
        const int rp = i / 12;             // 0..125
        const int r  = rp / 3;
        const int p  = rp - r * 3;
        const int gy = y0 + r;
        const int gx0 = bx * TW - 8 + q * 4;
        const bool ok = (gy >= 0) && (gy < IMH) && (gx0 >= 0) && (gx0 <= IMW - 4);

        const float* src = (p == 0) ? F : (p == 1) ? S1 : S2;
        float4 v = make_float4(0.f, 0.f, 0.f, 0.f);
        if (ok)
            v = *reinterpret_cast<const float4*>(src + plane + gy * IMW + gx0);

        const int cb = q * 4 - 3;          // raw col of v.x
        float* dst = &raw[p * EXT * RSTR + r * RSTR];
        if (cb + 0 >= 0 && cb + 0 < EXT) dst[cb + 0] = v.x;
        if (cb + 1 >= 0 && cb + 1 < EXT) dst[cb + 1] = v.y;
        if (cb + 2 >= 0 && cb + 2 < EXT) dst[cb + 2] = v.z;
        if (cb + 3 < EXT)                dst[cb + 3] = v.w;   // cb+3 >= 0 always
    }
    __syncthreads();

    // ---- Horizontal pass: 336 tasks (42 rows x 8 groups of 4 cols) --------
    for (int task = tid; task < EXT * 8; task += NTHREADS) {
        const int r  = task >> 3;
        const int c0 = (task & 7) * 4;

        float acc[8][4];
        #pragma unroll
        for (int k = 0; k < 8; ++k)
            #pragma unroll
            for (int o = 0; o < 4; ++o) acc[k][o] = 0.f;

        const float* r0p = &raw[0*EXT*RSTR + r*RSTR + c0];
        const float* r1p = &raw[1*EXT*RSTR + r*RSTR + c0];
        const float* r2p = &raw[2*EXT*RSTR + r*RSTR + c0];

        #pragma unroll
        for (int cc = 0; cc < 14; ++cc) {
            float f = r0p[cc], a = r1p[cc], b = r2p[cc];
            float v3 = f*f, v4 = a*a, v5 = b*b, v6 = f*a, v7 = f*b;
            #pragma unroll
            for (int o = 0; o < 4; ++o) {
                const int j = cc - o;
                if (j >= 0 && j < 11) {
                    const float w = WW(j);
                    acc[0][o] += w * f;   acc[1][o] += w * a;
                    acc[2][o] += w * b;   acc[3][o] += w * v3;
                    acc[4][o] += w * v4;  acc[5][o] += w * v5;
                    acc[6][o] += w * v6;  acc[7][o] += w * v7;
                }
            }
        }
        #pragma unroll
        for (int k = 0; k < 8; ++k) {
            float4 st = make_float4(acc[k][0], acc[k][1], acc[k][2], acc[k][3]);
            *reinterpret_cast<float4*>(&hint[k*EXT*HSTR + r*HSTR + c0]) = st;
        }
    }
    __syncthreads();

    // ---- Vertical pass + SSIM: thread = 1 column x 4 output rows ----------
    const int col = lane;
    const int r0v = wid * 4;

    float acc[8][4];
    #pragma unroll
    for (int k = 0; k < 8; ++k)
        #pragma unroll
        for (int o = 0; o < 4; ++o) acc[k][o] = 0.f;

    #pragma unroll
    for (int jj = 0; jj < 14; ++jj) {
        float v[8];
        #pragma unroll
        for (int k = 0; k < 8; ++k)
            v[k] = hint[k*EXT*HSTR + (r0v + jj)*HSTR + col];
        #pragma unroll
        for (int o = 0; o < 4; ++o) {
            const int j = jj - o;
            if (j >= 0 && j < 11) {
                const float w = WW(j);
                #pragma unroll
                for (int k = 0; k < 8; ++k) acc[k][o] += w * v[k];
            }
        }
    }

    const float C1 = 1e-4f;
    const float C2 = 9e-4f;
    float lsum = 0.f;
    #pragma unroll
    for (int o = 0; o < 4; ++o) {
        float muF = acc[0][o], mu1 = acc[1][o], mu2 = acc[2][o];
        float eFF = acc[3][o], e11 = acc[4][o], e22 = acc[5][o];
        float eF1 = acc[6][o], eF2 = acc[7][o];

        float mFF = muF*muF, m11 = mu1*mu1, m22 = mu2*mu2;
        float pF1 = muF*mu1, pF2 = muF*mu2;

        float sF  = eFF - mFF;
        float s11 = e11 - m11;
        float s22 = e22 - m22;
        float c1v = eF1 - pF1;
        float c2v = eF2 - pF2;

        float num1 = (2.f*pF1 + C1) * (2.f*c1v + C2);
        float den1 = (mFF + m11 + C1) * (sF + s11 + C2);
        float num2 = (2.f*pF2 + C1) * (2.f*c2v + C2);
        float den2 = (mFF + m22 + C1) * (sF + s22 + C2);

        lsum += __fdividef(num1*den2 + num2*den1, den1*den2);
    }

    // ---- Reduction: warp shuffle -> block -> Q32 atomic (48 slots) --------
    #pragma unroll
    for (int off = 16; off > 0; off >>= 1)
        lsum += __shfl_xor_sync(0xffffffffu, lsum, off);

    __shared__ float warpsum[8];
    __shared__ int   lastflag;
    if (lane == 0) warpsum[wid] = lsum;
    __syncthreads();
    if (tid == 0) {
        double s = 0.0;
        #pragma unroll
        for (int i = 0; i < 8; ++i) s += (double)warpsum[i];
        long long q = __double2ll_rn(s * FPSCALE);
        atomicAdd(&g_accs[bz], (u64)q);
        __threadfence();
        unsigned ticket = atomicInc(&g_count, NBLOCKS - 1);
        lastflag = (ticket == NBLOCKS - 1);
    }
    __syncthreads();

    if (lastflag) {
        __shared__ long long slotv[NPLANES];
        if (tid < NPLANES)
            slotv[tid] = (long long)atomicExch(&g_accs[tid], 0ULL);
        __syncthreads();
        if (tid == 0) {
            long long tot = 0;
            #pragma unroll
            for (int i = 0; i < NPLANES; ++i) tot += slotv[i];
            out[0] = (float)(1.0 - ((double)tot * (1.0/FPSCALE))
                                   / (2.0 * NTOT));
        }
    }
}

extern "C" void kernel_launch(void* const* d_in, const int* in_sizes, int n_in,
                              void* d_out, int out_size)
{
    const float* F  = (const float*)d_in[0];
    const float* S1 = (const float*)d_in[1];
    const float* S2 = (const float*)d_in[2];

    static bool attr_set = false;
    if (!attr_set) {
        cudaFuncSetAttribute(ssim_fused_kernel,
                             cudaFuncAttributeMaxDynamicSharedMemorySize,
                             SMEM_BYTES);
        attr_set = true;
    }

    dim3 grid(GX, GY, NPLANES);
    ssim_fused_kernel<<<grid, NTHREADS, SMEM_BYTES>>>(F, S1, S2, (float*)d_out);
}

// round 8
// speedup vs baseline: 1.6377x; 1.1683x over previous
#include <cuda_runtime.h>

// ---------------------------------------------------------------------------
// SSIM fusion loss: 1 - (SSIM(f,s1)+SSIM(f,s2))/2, single fused kernel.
// 4 CTAs/SM via phased smem aliasing (row-blocked hint over consumed raw),
// LDS.128 hpass loads, FFMA-immediate weights, Q32 deterministic reduction.
// ---------------------------------------------------------------------------

#define IMH 512
#define IMW 512
#define TW 32
#define TH 32
#define EXT 42
#define RSTR 44                  // raw per-plane row stride (16B-aligned cols)
#define RS3 132                  // raw row stride = 3*RSTR (interleaved planes)
#define HROW 288                 // hint row stride = 8 fields * 36
#define HSTR 36                  // per-field col stride inside a hint row
#define R1 30                    // phase-A hint rows (0..29)
#define HA_BASE 5544             // floats; = 42*132, 16B aligned
#define NTHREADS 256
#define GX 16
#define GY 16
#define NPLANES 48
#define NBLOCKS (GX*GY*NPLANES)
#define NTOT 12582912.0
#define FPSCALE 4294967296.0
#define SMEM_FLOATS (HA_BASE + R1*HROW)     // 5544 + 8640 = 14184
#define SMEM_BYTES  (SMEM_FLOATS*4)         // 56736 B -> 4 CTAs/SM

typedef unsigned long long u64;

__device__ u64      g_accs[NPLANES];        // zero-initialized
__device__ unsigned g_count = 0u;

// Gaussian weights (sigma=1.5, 11 taps, normalized) as pure literals ->
// FFMA with immediate multiplier (rt_SMSP = 1).
#define W0f 0.00102838f
#define W1f 0.00759876f
#define W2f 0.03600077f
#define W3f 0.10936069f
#define W4f 0.21300554f
#define W5f 0.26601173f
#define WW(j) ( (j)==5 ? W5f : ((j)==4||(j)==6) ? W4f : ((j)==3||(j)==7) ? W3f \
              : ((j)==2||(j)==8) ? W2f : ((j)==1||(j)==9) ? W1f : W0f )

// Horizontal blur of one raw row -> 8 fields x 4 cols, stored at STOREBASE.
#define HPASS_BODY(RAWBASE, STOREBASE)                                        \
{                                                                             \
    float fv[16], av[16], bv[16];                                             \
    _Pragma("unroll")                                                         \
    for (int q = 0; q < 4; ++q) {                                             \
        float4 Lf = *reinterpret_cast<const float4*>(&smem[(RAWBASE) + 0*RSTR + c0 + 4*q]); \
        float4 La = *reinterpret_cast<const float4*>(&smem[(RAWBASE) + 1*RSTR + c0 + 4*q]); \
        float4 Lb = *reinterpret_cast<const float4*>(&smem[(RAWBASE) + 2*RSTR + c0 + 4*q]); \
        fv[4*q+0]=Lf.x; fv[4*q+1]=Lf.y; fv[4*q+2]=Lf.z; fv[4*q+3]=Lf.w;       \
        av[4*q+0]=La.x; av[4*q+1]=La.y; av[4*q+2]=La.z; av[4*q+3]=La.w;       \
        bv[4*q+0]=Lb.x; bv[4*q+1]=Lb.y; bv[4*q+2]=Lb.z; bv[4*q+3]=Lb.w;       \
    }                                                                         \
    float acc[8][4];                                                          \
    _Pragma("unroll")                                                         \
    for (int k = 0; k < 8; ++k)                                               \
        _Pragma("unroll")                                                     \
        for (int o = 0; o < 4; ++o) acc[k][o] = 0.f;                          \
    _Pragma("unroll")                                                         \
    for (int cc = 0; cc < 14; ++cc) {                                         \
        float f = fv[cc], a = av[cc], b = bv[cc];                             \
        float v3 = f*f, v4 = a*a, v5 = b*b, v6 = f*a, v7 = f*b;               \
        _Pragma("unroll")                                                     \
        for (int o = 0; o < 4; ++o) {                                         \
            const int j = cc - o;                                             \
            if (j >= 0 && j < 11) {                                           \
                const float w = WW(j);                                        \
                acc[0][o] += w * f;   acc[1][o] += w * a;                     \
                acc[2][o] += w * b;   acc[3][o] += w * v3;                    \
                acc[4][o] += w * v4;  acc[5][o] += w * v5;                    \
                acc[6][o] += w * v6;  acc[7][o] += w * v7;                    \
            }                                                                 \
        }                                                                     \
    }                                                                         \
    _Pragma("unroll")                                                         \
    for (int k = 0; k < 8; ++k) {                                             \
        float4 st = make_float4(acc[k][0], acc[k][1], acc[k][2], acc[k][3]);  \
        *reinterpret_cast<float4*>(&smem[(STOREBASE) + k*HSTR + c0]) = st;    \
    }                                                                         \
}

__global__ __launch_bounds__(NTHREADS)
void ssim_fused_kernel(const float* __restrict__ F,
                       const float* __restrict__ S1,
                       const float* __restrict__ S2,
                       float* __restrict__ out)
{
    extern __shared__ float smem[];
    // [0 .. 5544)        raw[42][3][44]   (rows 0..26 later overlaid by hintB)
    // [5544 .. 14184)    hintA rows 0..29:  [30][8][36]
    // [0 .. 3456)        hintB rows 30..41: [12][8][36]   (phase B)

    const int tid  = threadIdx.x;
    const int wid  = tid >> 5;
    const int lane = tid & 31;

    const int bx = blockIdx.x, by = blockIdx.y, bz = blockIdx.z;
    const int plane = bz * (IMH * IMW);
    const int y0 = by * TH - 5;

    // ---- Vectorized halo load: 42 rows x 3 planes x 12 float4 chunks ------
    for (int i = tid; i < EXT * 3 * 12; i += NTHREADS) {
        const int q  = i % 12;
        const int rp = i / 12;
        const int r  = rp / 3;
        const int p  = rp - r * 3;
        const int gy = y0 + r;
        const int gx0 = bx * TW - 8 + q * 4;
        const bool ok = (gy >= 0) && (gy < IMH) && (gx0 >= 0) && (gx0 <= IMW - 4);

        const float* src = (p == 0) ? F : (p == 1) ? S1 : S2;
        float4 v = make_float4(0.f, 0.f, 0.f, 0.f);
        if (ok)
            v = *reinterpret_cast<const float4*>(src + plane + gy * IMW + gx0);

        const int cb = q * 4 - 3;
        float* dst = &smem[r * RS3 + p * RSTR];
        if (cb + 0 >= 0 && cb + 0 < EXT) dst[cb + 0] = v.x;
        if (cb + 1 >= 0 && cb + 1 < EXT) dst[cb + 1] = v.y;
        if (cb + 2 >= 0 && cb + 2 < EXT) dst[cb + 2] = v.z;
        if (cb + 3 < EXT)                dst[cb + 3] = v.w;
    }
    __syncthreads();

    // ---- Horizontal pass, phase A: rows 0..29 -> hintA --------------------
    if (tid < R1 * 8) {
        const int r  = tid >> 3;
        const int c0 = (tid & 7) * 4;
        HPASS_BODY(r * RS3, HA_BASE + r * HROW)
    }
    __syncthreads();

    // ---- Phase B: rows 30..41 -> hintB (overlays raw rows 0..26) ----------
    if (tid < 12 * 8) {
        const int rr = tid >> 3;            // 0..11 -> row 30+rr
        const int c0 = (tid & 7) * 4;
        HPASS_BODY((R1 + rr) * RS3, rr * HROW)
    }
    __syncthreads();

    // ---- Vertical pass + SSIM: thread = 1 column x 4 output rows ----------
    const int col = lane;
    const int r0v = wid * 4;

    float acc[8][4];
    #pragma unroll
    for (int k = 0; k < 8; ++k)
        #pragma unroll
        for (int o = 0; o < 4; ++o) acc[k][o] = 0.f;

    #pragma unroll
    for (int jj = 0; jj < 14; ++jj) {
        const int row = r0v + jj;
        const int rowbase = (row < R1) ? (HA_BASE + row * HROW)
                                       : ((row - R1) * HROW);
        float v[8];
        #pragma unroll
        for (int k = 0; k < 8; ++k)
            v[k] = smem[rowbase + k * HSTR + col];
        #pragma unroll
        for (int o = 0; o < 4; ++o) {
            const int j = jj - o;
            if (j >= 0 && j < 11) {
                const float w = WW(j);
                #pragma unroll
                for (int k = 0; k < 8; ++k) acc[k][o] += w * v[k];
            }
        }
    }

    const float C1 = 1e-4f;
    const float C2 = 9e-4f;
    float lsum = 0.f;
    #pragma unroll
    for (int o = 0; o < 4; ++o) {
        float muF = acc[0][o], mu1 = acc[1][o], mu2 = acc[2][o];
        float eFF = acc[3][o], e11 = acc[4][o], e22 = acc[5][o];
        float eF1 = acc[6][o], eF2 = acc[7][o];

        float mFF = muF*muF, m11 = mu1*mu1, m22 = mu2*mu2;
        float pF1 = muF*mu1, pF2 = muF*mu2;

        float sF  = eFF - mFF;
        float s11 = e11 - m11;
        float s22 = e22 - m22;
        float c1v = eF1 - pF1;
        float c2v = eF2 - pF2;

        float num1 = (2.f*pF1 + C1) * (2.f*c1v + C2);
        float den1 = (mFF + m11 + C1) * (sF + s11 + C2);
        float num2 = (2.f*pF2 + C1) * (2.f*c2v + C2);
        float den2 = (mFF + m22 + C1) * (sF + s22 + C2);

        lsum += __fdividef(num1*den2 + num2*den1, den1*den2);
    }

    // ---- Reduction: warp shuffle -> block -> Q32 atomic (48 slots) --------
    #pragma unroll
    for (int off = 16; off > 0; off >>= 1)
        lsum += __shfl_xor_sync(0xffffffffu, lsum, off);

    __shared__ float     warpsum[8];
    __shared__ int       lastflag;
    __shared__ long long fin[2];
    if (lane == 0) warpsum[wid] = lsum;
    __syncthreads();
    if (tid == 0) {
        double s = 0.0;
        #pragma unroll
        for (int i = 0; i < 8; ++i) s += (double)warpsum[i];
        long long q = __double2ll_rn(s * FPSCALE);
        atomicAdd(&g_accs[bz], (u64)q);
        __threadfence();
        unsigned ticket = atomicInc(&g_count, NBLOCKS - 1);
        lastflag = (ticket == NBLOCKS - 1);
    }
    __syncthreads();

    if (lastflag) {
        // Drain the 48 slots: warp 0 (32 slots) + warp 1 (16 slots).
        long long v = 0;
        if (tid < NPLANES)
            v = (long long)atomicExch(&g_accs[tid], 0ULL);
        if (wid < 2) {
            #pragma unroll
            for (int off = 16; off > 0; off >>= 1)
                v += __shfl_xor_sync(0xffffffffu, v, off);
            if (lane == 0) fin[wid] = v;
        }
        __syncthreads();
        if (tid == 0) {
            long long tot = fin[0] + fin[1];
            out[0] = (float)(1.0 - ((double)tot * (1.0/FPSCALE))
                                   / (2.0 * NTOT));
        }
    }
}

extern "C" void kernel_launch(void* const* d_in, const int* in_sizes, int n_in,
                              void* d_out, int out_size)
{
    const float* F  = (const float*)d_in[0];
    const float* S1 = (const float*)d_in[1];
    const float* S2 = (const float*)d_in[2];

    static bool attr_set = false;
    if (!attr_set) {
        cudaFuncSetAttribute(ssim_fused_kernel,
                             cudaFuncAttributeMaxDynamicSharedMemorySize,
                             SMEM_BYTES);
        attr_set = true;
    }

    dim3 grid(GX, GY, NPLANES);
    ssim_fused_kernel<<<grid, NTHREADS, SMEM_BYTES>>>(F, S1, S2, (float*)d_out);
}

// round 9
// speedup vs baseline: 1.6623x; 1.0150x over previous
#include <cuda_runtime.h>

// ---------------------------------------------------------------------------
// SSIM fusion loss: 1 - (SSIM(f,s1)+SSIM(f,s2))/2, single fused kernel.
// 4 CTAs/SM via phased smem aliasing; LDS.128 hpass loads; scalar FFMA-imm
// hpass; pair-interleaved hint + LDS.64/f32x2 vpass; Q32 reduction.
// ---------------------------------------------------------------------------

#define IMH 512
#define IMW 512
#define TW 32
#define TH 32
#define EXT 42
#define RSTR 44                  // raw per-plane row stride
#define RS3 132                  // raw row stride = 3*RSTR
#define HROW 288                 // hint row stride = 4 pairs * 72
#define PSTRIDE 72               // floats per pair within a row (36 colpairs*2)
#define R1 30                    // phase-A hint rows (0..29)
#define HA_BASE 5544             // = 42*132, 16B aligned
#define NTHREADS 256
#define GX 16
#define GY 16
#define NPLANES 48
#define NBLOCKS (GX*GY*NPLANES)
#define NTOT 12582912.0
#define FPSCALE 4294967296.0
#define SMEM_FLOATS (HA_BASE + R1*HROW)     // 14184
#define SMEM_BYTES  (SMEM_FLOATS*4)         // 56736 B -> 4 CTAs/SM

typedef unsigned long long u64;

__device__ u64      g_accs[NPLANES];
__device__ unsigned g_count = 0u;

// Gaussian weights (sigma=1.5, 11 taps, normalized) as pure literals.
#define W0f 0.00102838f
#define W1f 0.00759876f
#define W2f 0.03600077f
#define W3f 0.10936069f
#define W4f 0.21300554f
#define W5f 0.26601173f
#define WW(j) ( (j)==5 ? W5f : ((j)==4||(j)==6) ? W4f : ((j)==3||(j)==7) ? W3f \
              : ((j)==2||(j)==8) ? W2f : ((j)==1||(j)==9) ? W1f : W0f )

__device__ __forceinline__ u64 pack2(float lo, float hi) {
    u64 r;
    asm("mov.b64 %0, {%1, %2};" : "=l"(r)
        : "r"(__float_as_uint(lo)), "r"(__float_as_uint(hi)));
    return r;
}
__device__ __forceinline__ void unpack2(u64 v, float& lo, float& hi) {
    unsigned a, b;
    asm("mov.b64 {%0, %1}, %2;" : "=r"(a), "=r"(b) : "l"(v));
    lo = __uint_as_float(a); hi = __uint_as_float(b);
}
__device__ __forceinline__ u64 fma2(u64 a, u64 b, u64 c) {
    u64 d;
    asm("fma.rn.f32x2 %0, %1, %2, %3;" : "=l"(d) : "l"(a), "l"(b), "l"(c));
    return d;
}

// Horizontal blur of one raw row -> 8 fields x 4 cols, stored pair-interleaved
// at STOREBASE: pair p holds fields (2p,2p+1); col c at offset p*72 + c*2.
#define HPASS_BODY(RAWBASE, STOREBASE)                                        \
{                                                                             \
    float fv[16], av[16], bv[16];                                             \
    _Pragma("unroll")                                                         \
    for (int q = 0; q < 4; ++q) {                                             \
        float4 Lf = *reinterpret_cast<const float4*>(&smem[(RAWBASE) + 0*RSTR + c0 + 4*q]); \
        float4 La = *reinterpret_cast<const float4*>(&smem[(RAWBASE) + 1*RSTR + c0 + 4*q]); \
        float4 Lb = *reinterpret_cast<const float4*>(&smem[(RAWBASE) + 2*RSTR + c0 + 4*q]); \
        fv[4*q+0]=Lf.x; fv[4*q+1]=Lf.y; fv[4*q+2]=Lf.z; fv[4*q+3]=Lf.w;       \
        av[4*q+0]=La.x; av[4*q+1]=La.y; av[4*q+2]=La.z; av[4*q+3]=La.w;       \
        bv[4*q+0]=Lb.x; bv[4*q+1]=Lb.y; bv[4*q+2]=Lb.z; bv[4*q+3]=Lb.w;       \
    }                                                                         \
    float acc[8][4];                                                          \
    _Pragma("unroll")                                                         \
    for (int k = 0; k < 8; ++k)                                               \
        _Pragma("unroll")                                                     \
        for (int o = 0; o < 4; ++o) acc[k][o] = 0.f;                          \
    _Pragma("unroll")                                                         \
    for (int cc = 0; cc < 14; ++cc) {                                         \
        float f = fv[cc], a = av[cc], b = bv[cc];                             \
        float v3 = f*f, v4 = a*a, v5 = b*b, v6 = f*a, v7 = f*b;               \
        _Pragma("unroll")                                                     \
        for (int o = 0; o < 4; ++o) {                                         \
            const int j = cc - o;                                             \
            if (j >= 0 && j < 11) {                                           \
                const float w = WW(j);                                        \
                acc[0][o] += w * f;   acc[1][o] += w * a;                     \
                acc[2][o] += w * b;   acc[3][o] += w * v3;                    \
                acc[4][o] += w * v4;  acc[5][o] += w * v5;                    \
                acc[6][o] += w * v6;  acc[7][o] += w * v7;                    \
            }                                                                 \
        }                                                                     \
    }                                                                         \
    _Pragma("unroll")                                                         \
    for (int p = 0; p < 4; ++p) {                                             \
        float4 s0 = make_float4(acc[2*p][0], acc[2*p+1][0],                   \
                                acc[2*p][1], acc[2*p+1][1]);                  \
        float4 s1 = make_float4(acc[2*p][2], acc[2*p+1][2],                   \
                                acc[2*p][3], acc[2*p+1][3]);                  \
        *reinterpret_cast<float4*>(&smem[(STOREBASE) + p*PSTRIDE + c0*2    ]) = s0; \
        *reinterpret_cast<float4*>(&smem[(STOREBASE) + p*PSTRIDE + c0*2 + 4]) = s1; \
    }                                                                         \
}

__global__ __launch_bounds__(NTHREADS)
void ssim_fused_kernel(const float* __restrict__ F,
                       const float* __restrict__ S1,
                       const float* __restrict__ S2,
                       float* __restrict__ out)
{
    extern __shared__ float smem[];
    // [0 .. 5544)      raw[42][3][44]  (rows 0..26 later overlaid by hintB)
    // [5544 .. 14184)  hintA rows 0..29:  [30][4 pairs][72]
    // [0 .. 3456)      hintB rows 30..41: [12][4 pairs][72]

    const int tid  = threadIdx.x;
    const int wid  = tid >> 5;
    const int lane = tid & 31;

    const int bx = blockIdx.x, by = blockIdx.y, bz = blockIdx.z;
    const int plane = bz * (IMH * IMW);
    const int y0 = by * TH - 5;

    // ---- Vectorized halo load ---------------------------------------------
    for (int i = tid; i < EXT * 3 * 12; i += NTHREADS) {
        const int q  = i % 12;
        const int rp = i / 12;
        const int r  = rp / 3;
        const int p  = rp - r * 3;
        const int gy = y0 + r;
        const int gx0 = bx * TW - 8 + q * 4;
        const bool ok = (gy >= 0) && (gy < IMH) && (gx0 >= 0) && (gx0 <= IMW - 4);

        const float* src = (p == 0) ? F : (p == 1) ? S1 : S2;
        float4 v = make_float4(0.f, 0.f, 0.f, 0.f);
        if (ok)
            v = *reinterpret_cast<const float4*>(src + plane + gy * IMW + gx0);

        const int cb = q * 4 - 3;
        float* dst = &smem[r * RS3 + p * RSTR];
        if (cb + 0 >= 0 && cb + 0 < EXT) dst[cb + 0] = v.x;
        if (cb + 1 >= 0 && cb + 1 < EXT) dst[cb + 1] = v.y;
        if (cb + 2 >= 0 && cb + 2 < EXT) dst[cb + 2] = v.z;
        if (cb + 3 < EXT)                dst[cb + 3] = v.w;
    }
    __syncthreads();

    // ---- Horizontal pass, phase A: rows 0..29 -> hintA --------------------
    if (tid < R1 * 8) {
        const int r  = tid >> 3;
        const int c0 = (tid & 7) * 4;
        HPASS_BODY(r * RS3, HA_BASE + r * HROW)
    }
    __syncthreads();

    // ---- Phase B: rows 30..41 -> hintB (overlays raw rows 0..26) ----------
    if (tid < 12 * 8) {
        const int rr = tid >> 3;
        const int c0 = (tid & 7) * 4;
        HPASS_BODY((R1 + rr) * RS3, rr * HROW)
    }
    __syncthreads();

    // ---- Vertical pass (f32x2) + SSIM: thread = 1 col x 4 output rows -----
    const int col = lane;
    const int r0v = wid * 4;

    // packed (w,w) weights, 6 unique
    u64 wq[6];
    #pragma unroll
    for (int j = 0; j < 6; ++j) wq[j] = pack2(WW(j), WW(j));

    u64 acc[4][4];  // [pair][out]
    #pragma unroll
    for (int p = 0; p < 4; ++p)
        #pragma unroll
        for (int o = 0; o < 4; ++o) acc[p][o] = 0ULL;

    #pragma unroll
    for (int jj = 0; jj < 14; ++jj) {
        const int row = r0v + jj;
        const int rowbase = (row < R1) ? (HA_BASE + row * HROW)
                                       : ((row - R1) * HROW);
        u64 v[4];
        #pragma unroll
        for (int p = 0; p < 4; ++p)
            v[p] = *reinterpret_cast<const u64*>(&smem[rowbase + p*PSTRIDE + 2*col]);
        #pragma unroll
        for (int o = 0; o < 4; ++o) {
            const int j = jj - o;
            if (j >= 0 && j < 11) {
                const u64 w = wq[(j < 6) ? j : (10 - j)];
                #pragma unroll
                for (int p = 0; p < 4; ++p)
                    acc[p][o] = fma2(w, v[p], acc[p][o]);
            }
        }
    }

    const float C1 = 1e-4f;
    const float C2 = 9e-4f;
    float lsum = 0.f;
    #pragma unroll
    for (int o = 0; o < 4; ++o) {
        float muF, mu1, mu2, eFF, e11, e22, eF1, eF2;
        unpack2(acc[0][o], muF, mu1);
        unpack2(acc[1][o], mu2, eFF);
        unpack2(acc[2][o], e11, e22);
        unpack2(acc[3][o], eF1, eF2);

        float mFF = muF*muF, m11 = mu1*mu1, m22 = mu2*mu2;
        float pF1 = muF*mu1, pF2 = muF*mu2;

        float sF  = eFF - mFF;
        float s11 = e11 - m11;
        float s22 = e22 - m22;
        float c1v = eF1 - pF1;
        float c2v = eF2 - pF2;

        float num1 = (2.f*pF1 + C1) * (2.f*c1v + C2);
        float den1 = (mFF + m11 + C1) * (sF + s11 + C2);
        float num2 = (2.f*pF2 + C1) * (2.f*c2v + C2);
        float den2 = (mFF + m22 + C1) * (sF + s22 + C2);

        lsum += __fdividef(num1*den2 + num2*den1, den1*den2);
    }

    // ---- Reduction: warp shuffle -> block -> Q32 atomic (48 slots) --------
    #pragma unroll
    for (int off = 16; off > 0; off >>= 1)
        lsum += __shfl_xor_sync(0xffffffffu, lsum, off);

    __shared__ float     warpsum[8];
    __shared__ int       lastflag;
    __shared__ long long fin[2];
    if (lane == 0) warpsum[wid] = lsum;
    __syncthreads();
    if (tid == 0) {
        double s = 0.0;
        #pragma unroll
        for (int i = 0; i < 8; ++i) s += (double)warpsum[i];
        long long q = __double2ll_rn(s * FPSCALE);
        atomicAdd(&g_accs[bz], (u64)q);
        __threadfence();
        unsigned ticket = atomicInc(&g_count, NBLOCKS - 1);
        lastflag = (ticket == NBLOCKS - 1);
    }
    __syncthreads();

    if (lastflag) {
        long long v = 0;
        if (tid < NPLANES)
            v = (long long)atomicExch(&g_accs[tid], 0ULL);
        if (wid < 2) {
            #pragma unroll
            for (int off = 16; off > 0; off >>= 1)
                v += __shfl_xor_sync(0xffffffffu, v, off);
            if (lane == 0) fin[wid] = v;
        }
        __syncthreads();
        if (tid == 0) {
            long long tot = fin[0] + fin[1];
            out[0] = (float)(1.0 - ((double)tot * (1.0/FPSCALE))
                                   / (2.0 * NTOT));
        }
    }
}

extern "C" void kernel_launch(void* const* d_in, const int* in_sizes, int n_in,
                              void* d_out, int out_size)
{
    const float* F  = (const float*)d_in[0];
    const float* S1 = (const float*)d_in[1];
    const float* S2 = (const float*)d_in[2];

    static bool attr_set = false;
    if (!attr_set) {
        cudaFuncSetAttribute(ssim_fused_kernel,
                             cudaFuncAttributeMaxDynamicSharedMemorySize,
                             SMEM_BYTES);
        attr_set = true;
    }

    dim3 grid(GX, GY, NPLANES);
    ssim_fused_kernel<<<grid, NTHREADS, SMEM_BYTES>>>(F, S1, S2, (float*)d_out);
}

// round 10
// speedup vs baseline: 1.7859x; 1.0744x over previous
#include <cuda_runtime.h>
#include <cuda_fp16.h>

// ---------------------------------------------------------------------------
// SSIM fusion loss: 1 - (SSIM(f,s1)+SSIM(f,s2))/2, single fused kernel.
// 4-5 CTAs/SM: phased smem aliasing + fp16 (half2) blurred-field intermediate.
// hpass: fp32 FFMA-imm math, converts to half2 pairs. vpass: LDS.32 half2 +
// HFMA2. Deterministic Q32 fixed-point reduction, last-block finalize.
// ---------------------------------------------------------------------------

#define IMH 512
#define IMW 512
#define TW 32
#define TH 32
#define EXT 42
#define RSTR 44                  // raw per-plane row stride (floats)
#define RS3 132                  // raw row stride = 3*RSTR (floats)
#define HROW2 144                // hint row stride in half2 units (4 pairs * 36)
#define PST2 36                  // half2 units per pair within a row
#define R1 30                    // phase-A hint rows (0..29)
#define RAW_FLOATS 5544          // 42*132
#define NTHREADS 256
#define GX 16
#define GY 16
#define NPLANES 48
#define NBLOCKS (GX*GY*NPLANES)
#define NTOT 12582912.0
#define FPSCALE 4294967296.0
#define SMEM_BYTES (RAW_FLOATS*4 + R1*HROW2*4)   // 22176 + 17280 = 39456 B

typedef unsigned long long u64;

__device__ u64      g_accs[NPLANES];
__device__ unsigned g_count = 0u;

// Gaussian weights (sigma=1.5, 11 taps, normalized) as pure literals ->
// FFMA with immediate multiplier in the fp32 hpass.
#define W0f 0.00102838f
#define W1f 0.00759876f
#define W2f 0.03600077f
#define W3f 0.10936069f
#define W4f 0.21300554f
#define W5f 0.26601173f
#define WW(j) ( (j)==5 ? W5f : ((j)==4||(j)==6) ? W4f : ((j)==3||(j)==7) ? W3f \
              : ((j)==2||(j)==8) ? W2f : ((j)==1||(j)==9) ? W1f : W0f )

// Horizontal blur of one raw row -> 8 fields x 4 cols; convert to half2 pairs
// (field 2p, field 2p+1) and store 1 STS.128 per pair at H2BASE (half2 units).
#define HPASS_BODY(RAWBASE, H2BASE)                                           \
{                                                                             \
    float fv[16], av[16], bv[16];                                             \
    _Pragma("unroll")                                                         \
    for (int q = 0; q < 4; ++q) {                                             \
        float4 Lf = *reinterpret_cast<const float4*>(&smem[(RAWBASE) + 0*RSTR + c0 + 4*q]); \
        float4 La = *reinterpret_cast<const float4*>(&smem[(RAWBASE) + 1*RSTR + c0 + 4*q]); \
        float4 Lb = *reinterpret_cast<const float4*>(&smem[(RAWBASE) + 2*RSTR + c0 + 4*q]); \
        fv[4*q+0]=Lf.x; fv[4*q+1]=Lf.y; fv[4*q+2]=Lf.z; fv[4*q+3]=Lf.w;       \
        av[4*q+0]=La.x; av[4*q+1]=La.y; av[4*q+2]=La.z; av[4*q+3]=La.w;       \
        bv[4*q+0]=Lb.x; bv[4*q+1]=Lb.y; bv[4*q+2]=Lb.z; bv[4*q+3]=Lb.w;       \
    }                                                                         \
    float acc[8][4];                                                          \
    _Pragma("unroll")                                                         \
    for (int k = 0; k < 8; ++k)                                               \
        _Pragma("unroll")                                                     \
        for (int o = 0; o < 4; ++o) acc[k][o] = 0.f;                          \
    _Pragma("unroll")                                                         \
    for (int cc = 0; cc < 14; ++cc) {                                         \
        float f = fv[cc], a = av[cc], b = bv[cc];                             \
        float v3 = f*f, v4 = a*a, v5 = b*b, v6 = f*a, v7 = f*b;               \
        _Pragma("unroll")                                                     \
        for (int o = 0; o < 4; ++o) {                                         \
            const int j = cc - o;                                             \
            if (j >= 0 && j < 11) {                                           \
                const float w = WW(j);                                        \
                acc[0][o] += w * f;   acc[1][o] += w * a;                     \
                acc[2][o] += w * b;   acc[3][o] += w * v3;                    \
                acc[4][o] += w * v4;  acc[5][o] += w * v5;                    \
                acc[6][o] += w * v6;  acc[7][o] += w * v7;                    \
            }                                                                 \
        }                                                                     \
    }                                                                         \
    _Pragma("unroll")                                                         \
    for (int p = 0; p < 4; ++p) {                                             \
        __half2 h0 = __floats2half2_rn(acc[2*p][0], acc[2*p+1][0]);           \
        __half2 h1 = __floats2half2_rn(acc[2*p][1], acc[2*p+1][1]);           \
        __half2 h2 = __floats2half2_rn(acc[2*p][2], acc[2*p+1][2]);           \
        __half2 h3 = __floats2half2_rn(acc[2*p][3], acc[2*p+1][3]);           \
        uint4 st;                                                             \
        st.x = *reinterpret_cast<unsigned*>(&h0);                             \
        st.y = *reinterpret_cast<unsigned*>(&h1);                             \
        st.z = *reinterpret_cast<unsigned*>(&h2);                             \
        st.w = *reinterpret_cast<unsigned*>(&h3);                             \
        *reinterpret_cast<uint4*>(&hint2[(H2BASE) + p*PST2 + c0]) = st;       \
    }                                                                         \
}

__global__ __launch_bounds__(NTHREADS)
void ssim_fused_kernel(const float* __restrict__ F,
                       const float* __restrict__ S1,
                       const float* __restrict__ S2,
                       float* __restrict__ out)
{
    extern __shared__ float smem[];
    // [0 .. 22176)B      raw[42][3][44] fp32 (rows <=13 later overlaid)
    // [22176 .. 39456)B  hintA rows 0..29: [30][4 pairs][36] half2
    // [0 .. 6912)B       hintB rows 30..41: [12][4 pairs][36] half2
    __half2* hint2  = reinterpret_cast<__half2*>(smem);           // base for B
    __half2* hint2A = reinterpret_cast<__half2*>(smem + RAW_FLOATS);

    const int tid  = threadIdx.x;
    const int wid  = tid >> 5;
    const int lane = tid & 31;

    const int bx = blockIdx.x, by = blockIdx.y, bz = blockIdx.z;
    const int plane = bz * (IMH * IMW);
    const int y0 = by * TH - 5;

    // ---- Vectorized halo load ---------------------------------------------
    for (int i = tid; i < EXT * 3 * 12; i += NTHREADS) {
        const int q  = i % 12;
        const int rp = i / 12;
        const int r  = rp / 3;
        const int p  = rp - r * 3;
        const int gy = y0 + r;
        const int gx0 = bx * TW - 8 + q * 4;
        const bool ok = (gy >= 0) && (gy < IMH) && (gx0 >= 0) && (gx0 <= IMW - 4);

        const float* src = (p == 0) ? F : (p == 1) ? S1 : S2;
        float4 v = make_float4(0.f, 0.f, 0.f, 0.f);
        if (ok)
            v = *reinterpret_cast<const float4*>(src + plane + gy * IMW + gx0);

        const int cb = q * 4 - 3;
        float* dst = &smem[r * RS3 + p * RSTR];
        if (cb + 0 >= 0 && cb + 0 < EXT) dst[cb + 0] = v.x;
        if (cb + 1 >= 0 && cb + 1 < EXT) dst[cb + 1] = v.y;
        if (cb + 2 >= 0 && cb + 2 < EXT) dst[cb + 2] = v.z;
        if (cb + 3 < EXT)                dst[cb + 3] = v.w;
    }
    __syncthreads();

    // ---- Horizontal pass, phase A: rows 0..29 -> hintA (after raw) --------
    if (tid < R1 * 8) {
        const int r  = tid >> 3;
        const int c0 = (tid & 7) * 4;
        __half2* hp = hint2A;
        #define hint2 hp
        HPASS_BODY(r * RS3, r * HROW2)
        #undef hint2
    }
    __syncthreads();

    // ---- Phase B: rows 30..41 -> hintB at smem[0] (overlays raw rows <=13)
    if (tid < 12 * 8) {
        const int rr = tid >> 3;            // 0..11 -> row 30+rr
        const int c0 = (tid & 7) * 4;
        HPASS_BODY((R1 + rr) * RS3, rr * HROW2)
    }
    __syncthreads();

    // ---- Vertical pass (half2/HFMA2) + SSIM: thread = 1 col x 4 rows ------
    const int col = lane;
    const int r0v = wid * 4;

    __half2 wh[6];
    #pragma unroll
    for (int j = 0; j < 6; ++j) wh[j] = __floats2half2_rn(WW(j), WW(j));

    __half2 acc[4][4];  // [pair][out]
    #pragma unroll
    for (int p = 0; p < 4; ++p)
        #pragma unroll
        for (int o = 0; o < 4; ++o) acc[p][o] = __floats2half2_rn(0.f, 0.f);

    #pragma unroll
    for (int jj = 0; jj < 14; ++jj) {
        const int row = r0v + jj;
        const __half2* rowp = (row < R1) ? &hint2A[row * HROW2]
                                         : &hint2[(row - R1) * HROW2];
        __half2 v[4];
        #pragma unroll
        for (int p = 0; p < 4; ++p)
            v[p] = rowp[p * PST2 + col];
        #pragma unroll
        for (int o = 0; o < 4; ++o) {
            const int j = jj - o;
            if (j >= 0 && j < 11) {
                const __half2 w = wh[(j < 6) ? j : (10 - j)];
                #pragma unroll
                for (int p = 0; p < 4; ++p)
                    acc[p][o] = __hfma2(w, v[p], acc[p][o]);
            }
        }
    }

    const float C1 = 1e-4f;
    const float C2 = 9e-4f;
    float lsum = 0.f;
    #pragma unroll
    for (int o = 0; o < 4; ++o) {
        float muF = __low2float (acc[0][o]);
        float mu1 = __high2float(acc[0][o]);
        float mu2 = __low2float (acc[1][o]);
        float eFF = __high2float(acc[1][o]);
        float e11 = __low2float (acc[2][o]);
        float e22 = __high2float(acc[2][o]);
        float eF1 = __low2float (acc[3][o]);
        float eF2 = __high2float(acc[3][o]);

        float mFF = muF*muF, m11 = mu1*mu1, m22 = mu2*mu2;
        float pF1 = muF*mu1, pF2 = muF*mu2;

        float sF  = eFF - mFF;
        float s11 = e11 - m11;
        float s22 = e22 - m22;
        float c1v = eF1 - pF1;
        float c2v = eF2 - pF2;

        float num1 = (2.f*pF1 + C1) * (2.f*c1v + C2);
        float den1 = (mFF + m11 + C1) * (sF + s11 + C2);
        float num2 = (2.f*pF2 + C1) * (2.f*c2v + C2);
        float den2 = (mFF + m22 + C1) * (sF + s22 + C2);

        lsum += __fdividef(num1*den2 + num2*den1, den1*den2);
    }

    // ---- Reduction: warp shuffle -> block -> Q32 atomic (48 slots) --------
    #pragma unroll
    for (int off = 16; off > 0; off >>= 1)
        lsum += __shfl_xor_sync(0xffffffffu, lsum, off);

    __shared__ float     warpsum[8];
    __shared__ int       lastflag;
    __shared__ long long fin[2];
    if (lane == 0) warpsum[wid] = lsum;
    __syncthreads();
    if (tid == 0) {
        double s = 0.0;
        #pragma unroll
        for (int i = 0; i < 8; ++i) s += (double)warpsum[i];
        long long q = __double2ll_rn(s * FPSCALE);
        atomicAdd(&g_accs[bz], (u64)q);
        __threadfence();
        unsigned ticket = atomicInc(&g_count, NBLOCKS - 1);
        lastflag = (ticket == NBLOCKS - 1);
    }
    __syncthreads();

    if (lastflag) {
        long long v = 0;
        if (tid < NPLANES)
            v = (long long)atomicExch(&g_accs[tid], 0ULL);
        if (wid < 2) {
            #pragma unroll
            for (int off = 16; off > 0; off >>= 1)
                v += __shfl_xor_sync(0xffffffffu, v, off);
            if (lane == 0) fin[wid] = v;
        }
        __syncthreads();
        if (tid == 0) {
            long long tot = fin[0] + fin[1];
            out[0] = (float)(1.0 - ((double)tot * (1.0/FPSCALE))
                                   / (2.0 * NTOT));
        }
    }
}

extern "C" void kernel_launch(void* const* d_in, const int* in_sizes, int n_in,
                              void* d_out, int out_size)
{
    const float* F  = (const float*)d_in[0];
    const float* S1 = (const float*)d_in[1];
    const float* S2 = (const float*)d_in[2];

    static bool attr_set = false;
    if (!attr_set) {
        cudaFuncSetAttribute(ssim_fused_kernel,
                             cudaFuncAttributeMaxDynamicSharedMemorySize,
                             SMEM_BYTES);
        attr_set = true;
    }

    dim3 grid(GX, GY, NPLANES);
    ssim_fused_kernel<<<grid, NTHREADS, SMEM_BYTES>>>(F, S1, S2, (float*)d_out);
}

// round 11
// speedup vs baseline: 1.9105x; 1.0697x over previous
#include <cuda_runtime.h>
#include <cuda_fp16.h>

// ---------------------------------------------------------------------------
// SSIM fusion loss: 1 - (SSIM(f,s1)+SSIM(f,s2))/2, single fused kernel.
// 5 CTAs/SM: phased smem aliasing + fp16 hint + reg-lean streaming hpass
// (launch_bounds 256,5). hpass: fp32 FFMA-imm -> half2 pairs. vpass: LDS.32
// half2 + HFMA2, warp-specialized row base. Q32 deterministic reduction.
// ---------------------------------------------------------------------------

#define IMH 512
#define IMW 512
#define TW 32
#define TH 32
#define EXT 42
#define RSTR 44                  // raw per-plane row stride (floats)
#define RS3 132                  // raw row stride = 3*RSTR (floats)
#define HROW2 144                // hint row stride in half2 units (4 pairs * 36)
#define PST2 36                  // half2 units per pair within a row
#define R1 30                    // phase-A hint rows (0..29)
#define RAW_FLOATS 5544          // 42*132
#define NTHREADS 256
#define GX 16
#define GY 16
#define NPLANES 48
#define NBLOCKS (GX*GY*NPLANES)
#define NTOT 12582912.0
#define FPSCALE 4294967296.0
#define SMEM_BYTES (RAW_FLOATS*4 + R1*HROW2*4)   // 22176 + 17280 = 39456 B

typedef unsigned long long u64;

__device__ u64      g_accs[NPLANES];
__device__ unsigned g_count = 0u;

// Gaussian weights (sigma=1.5, 11 taps, normalized) as pure literals ->
// FFMA with immediate multiplier in the fp32 hpass.
#define W0f 0.00102838f
#define W1f 0.00759876f
#define W2f 0.03600077f
#define W3f 0.10936069f
#define W4f 0.21300554f
#define W5f 0.26601173f
#define WW(j) ( (j)==5 ? W5f : ((j)==4||(j)==6) ? W4f : ((j)==3||(j)==7) ? W3f \
              : ((j)==2||(j)==8) ? W2f : ((j)==1||(j)==9) ? W1f : W0f )

// Streaming horizontal blur of one raw row -> 8 fields x 4 cols as half2
// pairs. Loads one float4 triple per q and consumes it immediately (low
// register liveness); accumulation order (cc ascending) identical to R10.
#define HPASS_BODY(RAWBASE, H2BASE)                                           \
{                                                                             \
    float acc[8][4];                                                          \
    _Pragma("unroll")                                                         \
    for (int k = 0; k < 8; ++k)                                               \
        _Pragma("unroll")                                                     \
        for (int o = 0; o < 4; ++o) acc[k][o] = 0.f;                          \
    _Pragma("unroll")                                                         \
    for (int q = 0; q < 4; ++q) {                                             \
        float4 Lf = *reinterpret_cast<const float4*>(&smem[(RAWBASE) + 0*RSTR + c0 + 4*q]); \
        float4 La = *reinterpret_cast<const float4*>(&smem[(RAWBASE) + 1*RSTR + c0 + 4*q]); \
        float4 Lb = *reinterpret_cast<const float4*>(&smem[(RAWBASE) + 2*RSTR + c0 + 4*q]); \
        float qf[4] = {Lf.x, Lf.y, Lf.z, Lf.w};                               \
        float qa[4] = {La.x, La.y, La.z, La.w};                               \
        float qb[4] = {Lb.x, Lb.y, Lb.z, Lb.w};                               \
        _Pragma("unroll")                                                     \
        for (int t = 0; t < 4; ++t) {                                         \
            const int cc = 4*q + t;                                           \
            if (cc < 14) {                                                    \
                float f = qf[t], a = qa[t], b = qb[t];                        \
                float v3 = f*f, v4 = a*a, v5 = b*b, v6 = f*a, v7 = f*b;       \
                _Pragma("unroll")                                             \
                for (int o = 0; o < 4; ++o) {                                 \
                    const int j = cc - o;                                     \
                    if (j >= 0 && j < 11) {                                   \
                        const float w = WW(j);                                \
                        acc[0][o] += w * f;   acc[1][o] += w * a;             \
                        acc[2][o] += w * b;   acc[3][o] += w * v3;            \
                        acc[4][o] += w * v4;  acc[5][o] += w * v5;            \
                        acc[6][o] += w * v6;  acc[7][o] += w * v7;            \
                    }                                                         \
                }                                                             \
            }                                                                 \
        }                                                                     \
    }                                                                         \
    _Pragma("unroll")                                                         \
    for (int p = 0; p < 4; ++p) {                                             \
        __half2 h0 = __floats2half2_rn(acc[2*p][0], acc[2*p+1][0]);           \
        __half2 h1 = __floats2half2_rn(acc[2*p][1], acc[2*p+1][1]);           \
        __half2 h2 = __floats2half2_rn(acc[2*p][2], acc[2*p+1][2]);           \
        __half2 h3 = __floats2half2_rn(acc[2*p][3], acc[2*p+1][3]);           \
        uint4 st;                                                             \
        st.x = *reinterpret_cast<unsigned*>(&h0);                             \
        st.y = *reinterpret_cast<unsigned*>(&h1);                             \
        st.z = *reinterpret_cast<unsigned*>(&h2);                             \
        st.w = *reinterpret_cast<unsigned*>(&h3);                             \
        *reinterpret_cast<uint4*>(&hintS[(H2BASE) + p*PST2 + c0]) = st;       \
    }                                                                         \
}

// vpass accumulation over 14 hint rows starting at r0v; ROWPTR(row) yields
// the half2* base of that row.
#define VPASS_LOOP(ROWPTR)                                                    \
    _Pragma("unroll")                                                         \
    for (int jj = 0; jj < 14; ++jj) {                                         \
        const int row = r0v + jj;                                             \
        const __half2* rowp = ROWPTR(row);                                    \
        __half2 v[4];                                                         \
        _Pragma("unroll")                                                     \
        for (int p = 0; p < 4; ++p)                                           \
            v[p] = rowp[p * PST2 + col];                                      \
        _Pragma("unroll")                                                     \
        for (int o = 0; o < 4; ++o) {                                         \
            const int j = jj - o;                                             \
            if (j >= 0 && j < 11) {                                           \
                const __half2 w = wh[(j < 6) ? j : (10 - j)];                 \
                _Pragma("unroll")                                             \
                for (int p = 0; p < 4; ++p)                                   \
                    acc[p][o] = __hfma2(w, v[p], acc[p][o]);                  \
            }                                                                 \
        }                                                                     \
    }

__global__ __launch_bounds__(NTHREADS, 5)
void ssim_fused_kernel(const float* __restrict__ F,
                       const float* __restrict__ S1,
                       const float* __restrict__ S2,
                       float* __restrict__ out)
{
    extern __shared__ float smem[];
    // [0 .. 22176)B      raw[42][3][44] fp32 (rows <=13 later overlaid)
    // [22176 .. 39456)B  hintA rows 0..29: [30][4 pairs][36] half2
    // [0 .. 6912)B       hintB rows 30..41: [12][4 pairs][36] half2
    __half2* hint2B = reinterpret_cast<__half2*>(smem);
    __half2* hint2A = reinterpret_cast<__half2*>(smem + RAW_FLOATS);

    const int tid  = threadIdx.x;
    const int wid  = tid >> 5;
    const int lane = tid & 31;

    const int bx = blockIdx.x, by = blockIdx.y, bz = blockIdx.z;
    const int plane = bz * (IMH * IMW);
    const int y0 = by * TH - 5;

    // ---- Vectorized halo load ---------------------------------------------
    for (int i = tid; i < EXT * 3 * 12; i += NTHREADS) {
        const int q  = i % 12;
        const int rp = i / 12;
        const int r  = rp / 3;
        const int p  = rp - r * 3;
        const int gy = y0 + r;
        const int gx0 = bx * TW - 8 + q * 4;
        const bool ok = (gy >= 0) && (gy < IMH) && (gx0 >= 0) && (gx0 <= IMW - 4);

        const float* src = (p == 0) ? F : (p == 1) ? S1 : S2;
        float4 v = make_float4(0.f, 0.f, 0.f, 0.f);
        if (ok)
            v = *reinterpret_cast<const float4*>(src + plane + gy * IMW + gx0);

        const int cb = q * 4 - 3;
        float* dst = &smem[r * RS3 + p * RSTR];
        if (cb + 0 >= 0 && cb + 0 < EXT) dst[cb + 0] = v.x;
        if (cb + 1 >= 0 && cb + 1 < EXT) dst[cb + 1] = v.y;
        if (cb + 2 >= 0 && cb + 2 < EXT) dst[cb + 2] = v.z;
        if (cb + 3 < EXT)                dst[cb + 3] = v.w;
    }
    __syncthreads();

    // ---- Horizontal pass, phase A: rows 0..29 -> hintA --------------------
    if (tid < R1 * 8) {
        const int r  = tid >> 3;
        const int c0 = (tid & 7) * 4;
        __half2* hintS = hint2A;
        HPASS_BODY(r * RS3, r * HROW2)
    }
    __syncthreads();

    // ---- Phase B: rows 30..41 -> hintB at smem[0] (overlays raw rows <=13)
    if (tid < 12 * 8) {
        const int rr = tid >> 3;            // 0..11 -> row 30+rr
        const int c0 = (tid & 7) * 4;
        __half2* hintS = hint2B;
        HPASS_BODY((R1 + rr) * RS3, rr * HROW2)
    }
    __syncthreads();

    // ---- Vertical pass (half2/HFMA2) + SSIM: thread = 1 col x 4 rows ------
    const int col = lane;
    const int r0v = wid * 4;

    __half2 wh[6];
    #pragma unroll
    for (int j = 0; j < 6; ++j) wh[j] = __floats2half2_rn(WW(j), WW(j));

    __half2 acc[4][4];  // [pair][out]
    #pragma unroll
    for (int p = 0; p < 4; ++p)
        #pragma unroll
        for (int o = 0; o < 4; ++o) acc[p][o] = __floats2half2_rn(0.f, 0.f);

    #define ROWPTR_A(row)   (&hint2A[(row) * HROW2])
    #define ROWPTR_MIX(row) ((row) < R1 ? &hint2A[(row) * HROW2]              \
                                        : &hint2B[((row) - R1) * HROW2])
    if (r0v + 13 < R1) {        // warps 0..4: rows entirely in hintA
        VPASS_LOOP(ROWPTR_A)
    } else {                    // warps 5..7: mixed A/B rows
        VPASS_LOOP(ROWPTR_MIX)
    }

    const float C1 = 1e-4f;
    const float C2 = 9e-4f;
    float lsum = 0.f;
    #pragma unroll
    for (int o = 0; o < 4; ++o) {
        float muF = __low2float (acc[0][o]);
        float mu1 = __high2float(acc[0][o]);
        float mu2 = __low2float (acc[1][o]);
        float eFF = __high2float(acc[1][o]);
        float e11 = __low2float (acc[2][o]);
        float e22 = __high2float(acc[2][o]);
        float eF1 = __low2float (acc[3][o]);
        float eF2 = __high2float(acc[3][o]);

        float mFF = muF*muF, m11 = mu1*mu1, m22 = mu2*mu2;
        float pF1 = muF*mu1, pF2 = muF*mu2;

        float sF  = eFF - mFF;
        float s11 = e11 - m11;
        float s22 = e22 - m22;
        float c1v = eF1 - pF1;
        float c2v = eF2 - pF2;

        float num1 = (2.f*pF1 + C1) * (2.f*c1v + C2);
        float den1 = (mFF + m11 + C1) * (sF + s11 + C2);
        float num2 = (2.f*pF2 + C1) * (2.f*c2v + C2);
        float den2 = (mFF + m22 + C1) * (sF + s22 + C2);

        lsum += __fdividef(num1*den2 + num2*den1, den1*den2);
    }

    // ---- Reduction: warp shuffle -> block -> Q32 atomic (48 slots) --------
    #pragma unroll
    for (int off = 16; off > 0; off >>= 1)
        lsum += __shfl_xor_sync(0xffffffffu, lsum, off);

    __shared__ float     warpsum[8];
    __shared__ int       lastflag;
    __shared__ long long fin[2];
    if (lane == 0) warpsum[wid] = lsum;
    __syncthreads();
    if (tid == 0) {
        double s = 0.0;
        #pragma unroll
        for (int i = 0; i < 8; ++i) s += (double)warpsum[i];
        long long q = __double2ll_rn(s * FPSCALE);
        atomicAdd(&g_accs[bz], (u64)q);
        __threadfence();
        unsigned ticket = atomicInc(&g_count, NBLOCKS - 1);
        lastflag = (ticket == NBLOCKS - 1);
    }
    __syncthreads();

    if (lastflag) {
        long long v = 0;
        if (tid < NPLANES)
            v = (long long)atomicExch(&g_accs[tid], 0ULL);
        if (wid < 2) {
            #pragma unroll
            for (int off = 16; off > 0; off >>= 1)
                v += __shfl_xor_sync(0xffffffffu, v, off);
            if (lane == 0) fin[wid] = v;
        }
        __syncthreads();
        if (tid == 0) {
            long long tot = fin[0] + fin[1];
            out[0] = (float)(1.0 - ((double)tot * (1.0/FPSCALE))
                                   / (2.0 * NTOT));
        }
    }
}

extern "C" void kernel_launch(void* const* d_in, const int* in_sizes, int n_in,
                              void* d_out, int out_size)
{
    const float* F  = (const float*)d_in[0];
    const float* S1 = (const float*)d_in[1];
    const float* S2 = (const float*)d_in[2];

    static bool attr_set = false;
    if (!attr_set) {
        cudaFuncSetAttribute(ssim_fused_kernel,
                             cudaFuncAttributeMaxDynamicSharedMemorySize,
                             SMEM_BYTES);
        attr_set = true;
    }

    dim3 grid(GX, GY, NPLANES);
    ssim_fused_kernel<<<grid, NTHREADS, SMEM_BYTES>>>(F, S1, S2, (float*)d_out);
}